// round 2
// baseline (speedup 1.0000x reference)
#include <cuda_runtime.h>

typedef unsigned long long u64;

#define NT 448
#define BT 56
#define RSTR 58
#define B_TOT 8192
#define T_STEPS 30
#define WARM 24

__device__ __forceinline__ u64 pack2(float lo, float hi){
    u64 r; asm("mov.b64 %0, {%1, %2};" : "=l"(r) : "f"(lo), "f"(hi)); return r;
}
__device__ __forceinline__ void unpack2(u64 v, float& lo, float& hi){
    asm("mov.b64 {%0, %1}, %2;" : "=f"(lo), "=f"(hi) : "l"(v));
}
__device__ __forceinline__ u64 fma2(u64 a, u64 b, u64 c){
    u64 d; asm("fma.rn.f32x2 %0, %1, %2, %3;" : "=l"(d) : "l"(a), "l"(b), "l"(c)); return d;
}
__device__ __forceinline__ float sig_(float x){ return __fdividef(1.f, 1.f + __expf(-x)); }
__device__ __forceinline__ float tanh_(float x){ return 1.f - 2.f * __fdividef(1.f, __expf(2.f * x) + 1.f); }

__device__ __forceinline__ void gemm_step(u64 (&acc)[4][8], const float* __restrict__ srow,
                                          const float* __restrict__ wrow, int rg, int cg){
    u64 hp[4];
    const u64* h64 = reinterpret_cast<const u64*>(srow + (rg << 3));
    #pragma unroll
    for (int rp = 0; rp < 4; rp++) hp[rp] = h64[rp];
    #pragma unroll
    for (int q = 0; q < 4; q++){
        u64 wp = *reinterpret_cast<const u64*>(wrow + (q << 7) + (cg << 1));
        float w0, w1; unpack2(wp, w0, w1);
        u64 w00 = pack2(w0, w0), w11 = pack2(w1, w1);
        #pragma unroll
        for (int rp = 0; rp < 4; rp++){
            acc[rp][(q<<1)  ] = fma2(hp[rp], w00, acc[rp][(q<<1)  ]);
            acc[rp][(q<<1)+1] = fma2(hp[rp], w11, acc[rp][(q<<1)+1]);
        }
    }
}

__device__ __forceinline__ void mlp_step(u64 (&acc)[4][2], const float* __restrict__ srow,
                                         const float* __restrict__ wrow, int rg, int cg){
    u64 hp[4];
    const u64* h64 = reinterpret_cast<const u64*>(srow + (rg << 3));
    #pragma unroll
    for (int rp = 0; rp < 4; rp++) hp[rp] = h64[rp];
    u64 wp = *reinterpret_cast<const u64*>(wrow + (cg << 1));
    float w0, w1; unpack2(wp, w0, w1);
    u64 w00 = pack2(w0, w0), w11 = pack2(w1, w1);
    #pragma unroll
    for (int rp = 0; rp < 4; rp++){
        acc[rp][0] = fma2(hp[rp], w00, acc[rp][0]);
        acc[rp][1] = fma2(hp[rp], w11, acc[rp][1]);
    }
}

#define SMEM_FLOATS (392*RSTR + 8*BT + BT + 512 + 128 + 128 + 128)
#define SMEM_BYTES (SMEM_FLOATS * 4)

__global__ void __launch_bounds__(NT, 1)
fused_lstm_kernel(const float* __restrict__ x0, const float* __restrict__ x1,
                  const float* __restrict__ x2, const float* __restrict__ x3,
                  const float* __restrict__ x4, const float* __restrict__ x5,
                  const float* __restrict__ x6, const float* __restrict__ irr,
                  const float* __restrict__ Wi, const float* __restrict__ Wh,
                  const float* __restrict__ bz, const float* __restrict__ W1,
                  const float* __restrict__ b1, const float* __restrict__ W2,
                  const float* __restrict__ b2, const float* __restrict__ Wout,
                  const float* __restrict__ bout, float* __restrict__ out)
{
    extern __shared__ float smem[];
    float* hbuf  = smem;               // [136][RSTR]: rows 0-127 h (k-major), 128-135 inputs
    float* m1buf = hbuf  + 136*RSTR;   // [128][RSTR]
    float* m2buf = m1buf + 128*RSTR;   // [128][RSTR]
    float* red   = m2buf + 128*RSTR;   // [8][BT]
    float* predb = red   + 8*BT;       // [BT]
    float* cb    = predb + BT;         // [512]
    float* cb1   = cb    + 512;        // [128]
    float* cb2   = cb1   + 128;        // [128]
    float* cwout = cb2   + 128;        // [128]

    const int tid = threadIdx.x;
    const int rg = tid >> 6, cg = tid & 63;
    const int lf = tid / BT, lr = tid - lf * BT;
    const int b0 = blockIdx.x * BT;

    for (int i = tid; i < 128*RSTR; i += NT) hbuf[i] = 0.f;
    for (int i = tid; i < 512; i += NT) cb[i] = bz[i];
    if (tid < 128){ cb1[tid] = b1[tid]; cb2[tid] = b2[tid]; cwout[tid] = Wout[tid]; }
    const float boutv = bout[0];

    int lb = b0 + lr; if (lb > B_TOT - 1) lb = B_TOT - 1;
    const float* fptr;
    if      (lf == 0) fptr = x0; else if (lf == 1) fptr = x1;
    else if (lf == 2) fptr = x2; else if (lf == 3) fptr = x3;
    else if (lf == 4) fptr = x4; else if (lf == 5) fptr = x5;
    else if (lf == 6) fptr = x6; else fptr = irr;
    fptr = (lf < 7) ? (fptr + lb * T_STEPS) : (fptr + lb * WARM);
    const int tmax = (lf < 7) ? (T_STEPS - 1) : (WARM - 1);

    u64 cst[4][2];
    #pragma unroll
    for (int rp = 0; rp < 4; rp++){ cst[rp][0] = 0ull; cst[rp][1] = 0ull; }

    __syncthreads();

    for (int t = 0; t < T_STEPS; ++t){
        { // stage inputs (transposed) into hbuf rows 128..135
            int ti = t < tmax ? t : tmax;
            float gv = __ldg(fptr + ti);
            float v = (lf < 7 || t < WARM) ? gv : predb[lr];
            hbuf[(128 + lf) * RSTR + lr] = v;
        }
        __syncthreads();

        u64 acc[4][8];
        #pragma unroll
        for (int q = 0; q < 4; q++)
            #pragma unroll
            for (int d = 0; d < 2; d++){
                float bv = cb[(q<<7) + (cg<<1) + d];
                u64 p = pack2(bv, bv);
                #pragma unroll
                for (int rp = 0; rp < 4; rp++) acc[rp][(q<<1)+d] = p;
            }
        #pragma unroll 4
        for (int k = 0; k < 128; k++) gemm_step(acc, hbuf + k*RSTR, Wh + (k<<9), rg, cg);
        #pragma unroll
        for (int f = 0; f < 8; f++) gemm_step(acc, hbuf + (128+f)*RSTR, Wi + (f<<9), rg, cg);

        __syncthreads();

        #pragma unroll
        for (int rp = 0; rp < 4; rp++)
            #pragma unroll
            for (int d = 0; d < 2; d++){
                float zi0,zi1,zf0,zf1,zg0,zg1,zo0,zo1,c0,c1;
                unpack2(acc[rp][0+d], zi0, zi1);
                unpack2(acc[rp][2+d], zf0, zf1);
                unpack2(acc[rp][4+d], zg0, zg1);
                unpack2(acc[rp][6+d], zo0, zo1);
                unpack2(cst[rp][d], c0, c1);
                c0 = sig_(zf0)*c0 + sig_(zi0)*tanh_(zg0);
                c1 = sig_(zf1)*c1 + sig_(zi1)*tanh_(zg1);
                cst[rp][d] = pack2(c0, c1);
                float h0 = sig_(zo0)*tanh_(c0);
                float h1 = sig_(zo1)*tanh_(c1);
                *reinterpret_cast<u64*>(&hbuf[((cg<<1)+d)*RSTR + (rg<<3) + (rp<<1)]) = pack2(h0, h1);
            }
        __syncthreads();

        { // m1 = relu(h @ W1 + b1)
            u64 ma[4][2];
            float q0 = cb1[cg<<1], q1 = cb1[(cg<<1)+1];
            u64 p0 = pack2(q0,q0), p1 = pack2(q1,q1);
            #pragma unroll
            for (int rp = 0; rp < 4; rp++){ ma[rp][0]=p0; ma[rp][1]=p1; }
            #pragma unroll 4
            for (int k = 0; k < 128; k++) mlp_step(ma, hbuf + k*RSTR, W1 + (k<<7), rg, cg);
            #pragma unroll
            for (int rp = 0; rp < 4; rp++)
                #pragma unroll
                for (int d = 0; d < 2; d++){
                    float v0,v1; unpack2(ma[rp][d], v0, v1);
                    *reinterpret_cast<u64*>(&m1buf[((cg<<1)+d)*RSTR + (rg<<3) + (rp<<1)]) =
                        pack2(fmaxf(v0,0.f), fmaxf(v1,0.f));
                }
        }
        __syncthreads();

        { // m2 = relu(m1 @ W2 + b2)
            u64 ma[4][2];
            float q0 = cb2[cg<<1], q1 = cb2[(cg<<1)+1];
            u64 p0 = pack2(q0,q0), p1 = pack2(q1,q1);
            #pragma unroll
            for (int rp = 0; rp < 4; rp++){ ma[rp][0]=p0; ma[rp][1]=p1; }
            #pragma unroll 4
            for (int k = 0; k < 128; k++) mlp_step(ma, m1buf + k*RSTR, W2 + (k<<7), rg, cg);
            #pragma unroll
            for (int rp = 0; rp < 4; rp++)
                #pragma unroll
                for (int d = 0; d < 2; d++){
                    float v0,v1; unpack2(ma[rp][d], v0, v1);
                    *reinterpret_cast<u64*>(&m2buf[((cg<<1)+d)*RSTR + (rg<<3) + (rp<<1)]) =
                        pack2(fmaxf(v0,0.f), fmaxf(v1,0.f));
                }
        }
        __syncthreads();

        { // pred = m2 @ Wout + bout
            float part = 0.f;
            #pragma unroll
            for (int i = 0; i < 16; i++){
                int k = (lf<<4) + i;
                part += m2buf[k*RSTR + lr] * cwout[k];
            }
            red[lf*BT + lr] = part;
        }
        __syncthreads();
        if (tid < BT){
            float s = boutv;
            #pragma unroll
            for (int g = 0; g < 8; g++) s += red[g*BT + tid];
            predb[tid] = s;
            int bb = b0 + tid;
            if (bb < B_TOT) out[bb*T_STEPS + t] = s;
        }
        __syncthreads();
    }
}

extern "C" void kernel_launch(void* const* d_in, const int* in_sizes, int n_in,
                              void* d_out, int out_size)
{
    (void)in_sizes; (void)n_in; (void)out_size;
    // metadata order: 0-7 weather (unused), 8-14 time feats, 15 irradiance_in,
    // 16 Wi, 17 Wh, 18 b, 19 W1, 20 b1, 21 W2, 22 b2, 23 Wout, 24 bout
    cudaFuncSetAttribute(fused_lstm_kernel, cudaFuncAttributeMaxDynamicSharedMemorySize, SMEM_BYTES);
    int grid = (B_TOT + BT - 1) / BT; // 147
    fused_lstm_kernel<<<grid, NT, SMEM_BYTES>>>(
        (const float*)d_in[8],  (const float*)d_in[9],  (const float*)d_in[10],
        (const float*)d_in[11], (const float*)d_in[12], (const float*)d_in[13],
        (const float*)d_in[14], (const float*)d_in[15],
        (const float*)d_in[16], (const float*)d_in[17], (const float*)d_in[18],
        (const float*)d_in[19], (const float*)d_in[20], (const float*)d_in[21],
        (const float*)d_in[22], (const float*)d_in[23], (const float*)d_in[24],
        (float*)d_out);
}